// round 3
// baseline (speedup 1.0000x reference)
#include <cuda_runtime.h>
#include <math.h>

// Problem constants
#define BB   32
#define DD   1024
#define NI_  1024
#define PP   1000
#define RR   3
#define SCALE 0.03125f   // 1/sqrt(1024)
#define SPLITK 8
#define KC   32

// ---------------------------------------------------------------------------
// Scratch (device globals; no allocation allowed)
// ---------------------------------------------------------------------------
__device__ float g_qall_part  [SPLITK * RR * BB * DD];   // 8 slabs of 98304
__device__ float g_scores_part[SPLITK * RR * BB * PP];   // 8 slabs of 96000
__device__ float g_weights    [RR * BB * PP];
__device__ float g_vagg_part  [SPLITK * RR * BB * DD];   // 24 slabs of 32768
__device__ float g_vagg       [BB * DD];
__device__ float g_q_part     [SPLITK * BB * DD];
__device__ float g_k_part     [SPLITK * BB * DD];
__device__ float g_v_part     [SPLITK * BB * DD];
__device__ float g_x          [BB * DD];
__device__ float g_vdraw_part [SPLITK * BB * DD];
__device__ float g_vdiff      [BB * DD];
__device__ float g_vdwg2      [BB];

// ---------------------------------------------------------------------------
// Block reductions (small kernels only)
// ---------------------------------------------------------------------------
__device__ __forceinline__ float block_sum(float v, float* red) {
    #pragma unroll
    for (int o = 16; o > 0; o >>= 1) v += __shfl_xor_sync(0xffffffffu, v, o);
    int w = threadIdx.x >> 5, l = threadIdx.x & 31;
    if (l == 0) red[w] = v;
    __syncthreads();
    if (w == 0) {
        float x = (l < (int)(blockDim.x >> 5)) ? red[l] : 0.f;
        #pragma unroll
        for (int o = 4; o > 0; o >>= 1) x += __shfl_xor_sync(0xffffffffu, x, o);
        if (l == 0) red[0] = x;
    }
    __syncthreads();
    float r = red[0];
    __syncthreads();
    return r;
}

__device__ __forceinline__ float block_max(float v, float* red) {
    #pragma unroll
    for (int o = 16; o > 0; o >>= 1) v = fmaxf(v, __shfl_xor_sync(0xffffffffu, v, o));
    int w = threadIdx.x >> 5, l = threadIdx.x & 31;
    if (l == 0) red[w] = v;
    __syncthreads();
    if (w == 0) {
        float x = (l < (int)(blockDim.x >> 5)) ? red[l] : -1e30f;
        #pragma unroll
        for (int o = 4; o > 0; o >>= 1) x = fmaxf(x, __shfl_xor_sync(0xffffffffu, x, o));
        if (l == 0) red[0] = x;
    }
    __syncthreads();
    float r = red[0];
    __syncthreads();
    return r;
}

// ---------------------------------------------------------------------------
// Generic skinny GEMM:  C[m][n] = alpha * sum_k A[m][k] * Bop[k][n]
//   A: row-major [M,K], lda. If nslabA>1, A element = sum over nslabA slabs
//   spaced sAslab apart (slab-reduction fused into the A stage; only valid
//   when K % KC == 0, which holds for all nslabA>1 call sites here).
//   B: bkn==0 -> B is [N,K] row-major;  bkn==1 -> B is [K,N] row-major.
//   Tiles: 32 (M) x 64 (N), KC=32, 128 threads, 4x4 micro-tile.
//   Split-K: SPLITK output slabs (deterministic, no atomics).
//   grid.x = ntilesN*SPLITK, grid.y = M/32, grid.z = batch
// ---------------------------------------------------------------------------
__global__ __launch_bounds__(128) void gemm_kernel(
    const float* __restrict__ A, int lda, long sAz, int nslabA, long sAslab,
    const float* __restrict__ B, int ldb, long sBz,
    float* __restrict__ C, int ldc, long sCz, long sCkp,
    int N, int K, float alpha, int bkn)
{
    const int nt = blockIdx.x / SPLITK;
    const int kp = blockIdx.x % SPLITK;
    const int n0 = nt * 64;
    const int m0 = blockIdx.y * 32;

    const float* Ap = A + (long)blockIdx.z * sAz + (long)m0 * lda;
    const float* Bp = B + (long)blockIdx.z * sBz;
    float*       Cp = C + (long)kp * sCkp + (long)blockIdx.z * sCz + (long)m0 * ldc;

    __shared__ float As[KC][36];
    __shared__ float Bs[KC][68];

    const int t  = threadIdx.x;
    const int tm = t >> 4;
    const int tn = t & 15;

    float acc[4][4];
    #pragma unroll
    for (int i = 0; i < 4; i++)
        #pragma unroll
        for (int j = 0; j < 4; j++) acc[i][j] = 0.f;

    const int nch = (K + KC - 1) / KC;
    for (int c = kp; c < nch; c += SPLITK) {
        const int k0 = c * KC;
        int kcur = K - k0; if (kcur > KC) kcur = KC;
        const bool full = (kcur == KC);

        // ---- load A chunk (32m x 32k), summing slabs, store As[k][m] ----
        #pragma unroll
        for (int i = 0; i < 2; i++) {
            int f4 = t + 128 * i;
            int m  = f4 >> 3;
            int kq = (f4 & 7) << 2;
            float4 av = make_float4(0.f, 0.f, 0.f, 0.f);
            const float* ap = Ap + (long)m * lda + k0 + kq;
            if (full) {
                for (int s = 0; s < nslabA; s++) {
                    float4 t4 = *reinterpret_cast<const float4*>(ap + (long)s * sAslab);
                    av.x += t4.x; av.y += t4.y; av.z += t4.z; av.w += t4.w;
                }
            } else {            // only reached with nslabA == 1
                float* pv = &av.x;
                #pragma unroll
                for (int j = 0; j < 4; j++)
                    if (kq + j < kcur) pv[j] = ap[j];
            }
            As[kq + 0][m] = av.x; As[kq + 1][m] = av.y;
            As[kq + 2][m] = av.z; As[kq + 3][m] = av.w;
        }

        // ---- load B chunk (64n x 32k) into Bs[k][n] ----
        if (!bkn) {
            #pragma unroll
            for (int i = 0; i < 4; i++) {
                int f4 = t + 128 * i;
                int n  = f4 >> 3;
                int kq = (f4 & 7) << 2;
                float4 bv = make_float4(0.f, 0.f, 0.f, 0.f);
                int gn = n0 + n;
                if (gn < N) {
                    if (full) {
                        bv = *reinterpret_cast<const float4*>(Bp + (long)gn * ldb + k0 + kq);
                    } else {
                        float* pv = &bv.x;
                        #pragma unroll
                        for (int j = 0; j < 4; j++)
                            if (kq + j < kcur) pv[j] = Bp[(long)gn * ldb + k0 + kq + j];
                    }
                }
                Bs[kq + 0][n] = bv.x; Bs[kq + 1][n] = bv.y;
                Bs[kq + 2][n] = bv.z; Bs[kq + 3][n] = bv.w;
            }
        } else {
            #pragma unroll
            for (int i = 0; i < 4; i++) {
                int f4 = t + 128 * i;
                int kc = f4 >> 4;
                int nq = (f4 & 15) << 2;
                float4 bv = make_float4(0.f, 0.f, 0.f, 0.f);
                int gn = n0 + nq;
                if (kc < kcur) {
                    if (gn + 3 < N) {
                        bv = *reinterpret_cast<const float4*>(Bp + (long)(k0 + kc) * ldb + gn);
                    } else {
                        float* pv = &bv.x;
                        #pragma unroll
                        for (int j = 0; j < 4; j++)
                            if (gn + j < N) pv[j] = Bp[(long)(k0 + kc) * ldb + gn + j];
                    }
                }
                *reinterpret_cast<float4*>(&Bs[kc][nq]) = bv;
            }
        }
        __syncthreads();

        // ---- compute ----
        #pragma unroll 8
        for (int kc = 0; kc < KC; kc++) {
            float4 a = *reinterpret_cast<const float4*>(&As[kc][tm << 2]);
            float4 b = *reinterpret_cast<const float4*>(&Bs[kc][tn << 2]);
            acc[0][0] = fmaf(a.x, b.x, acc[0][0]);
            acc[0][1] = fmaf(a.x, b.y, acc[0][1]);
            acc[0][2] = fmaf(a.x, b.z, acc[0][2]);
            acc[0][3] = fmaf(a.x, b.w, acc[0][3]);
            acc[1][0] = fmaf(a.y, b.x, acc[1][0]);
            acc[1][1] = fmaf(a.y, b.y, acc[1][1]);
            acc[1][2] = fmaf(a.y, b.z, acc[1][2]);
            acc[1][3] = fmaf(a.y, b.w, acc[1][3]);
            acc[2][0] = fmaf(a.z, b.x, acc[2][0]);
            acc[2][1] = fmaf(a.z, b.y, acc[2][1]);
            acc[2][2] = fmaf(a.z, b.z, acc[2][2]);
            acc[2][3] = fmaf(a.z, b.w, acc[2][3]);
            acc[3][0] = fmaf(a.w, b.x, acc[3][0]);
            acc[3][1] = fmaf(a.w, b.y, acc[3][1]);
            acc[3][2] = fmaf(a.w, b.z, acc[3][2]);
            acc[3][3] = fmaf(a.w, b.w, acc[3][3]);
        }
        __syncthreads();
    }

    // ---- store partial (per-kp slab; deterministic) ----
    #pragma unroll
    for (int i = 0; i < 4; i++) {
        long rowoff = (long)((tm << 2) + i) * ldc;
        #pragma unroll
        for (int j = 0; j < 4; j++) {
            int gn = n0 + (tn << 2) + j;
            if (gn < N) Cp[rowoff + gn] = acc[i][j] * alpha;
        }
    }
}

// ---------------------------------------------------------------------------
// Sum nslabs contiguous slabs of `elems` floats
// ---------------------------------------------------------------------------
__global__ __launch_bounds__(256) void reduce_slabs_kernel(
    const float* __restrict__ src, float* __restrict__ dst, int elems, int nslabs)
{
    int i = blockIdx.x * 256 + threadIdx.x;
    if (i < elems) {
        float s = 0.f;
        for (int k = 0; k < nslabs; k++) s += src[(long)k * elems + i];
        dst[i] = s;
    }
}

// ---------------------------------------------------------------------------
// Softmax over P for each of the 96 rows; input = SPLITK slabs of scores
// ---------------------------------------------------------------------------
__global__ __launch_bounds__(256) void softmax_kernel(
    const float* __restrict__ sp, float* __restrict__ w)
{
    const int row = blockIdx.x;
    const int t = threadIdx.x;
    __shared__ float buf[PP];
    __shared__ float red[8];
    const long base = (long)row * PP;
    const long slab = (long)RR * BB * PP;

    float mx = -1e30f;
    for (int p = t; p < PP; p += 256) {
        float s = 0.f;
        #pragma unroll
        for (int k = 0; k < SPLITK; k++) s += sp[(long)k * slab + base + p];
        buf[p] = s;
        mx = fmaxf(mx, s);
    }
    float m = block_max(mx, red);

    float sum = 0.f;
    for (int p = t; p < PP; p += 256) {
        float e = __expf(buf[p] - m);
        buf[p] = e;
        sum += e;
    }
    float S = block_sum(sum, red);
    float inv = 1.f / S;
    for (int p = t; p < PP; p += 256) w[base + p] = buf[p] * inv;
}

// ---------------------------------------------------------------------------
// sim = <q+bq, k+bk>*scale per batch; x = vhat - sigmoid(sim)*(v+bv)
// ---------------------------------------------------------------------------
__global__ __launch_bounds__(256) void simx_kernel(
    const float* __restrict__ qp, const float* __restrict__ kp,
    const float* __restrict__ vp,
    const float* __restrict__ bq, const float* __restrict__ bk,
    const float* __restrict__ bv,
    const float* __restrict__ fc, float* __restrict__ x)
{
    const int b = blockIdx.x;
    const int t = threadIdx.x;
    __shared__ float red[8];
    const long slab = (long)BB * DD;

    float partial = 0.f;
    for (int d = t; d < DD; d += 256) {
        long idx = (long)b * DD + d;
        float qv = bq[d], kv = bk[d];
        #pragma unroll
        for (int s = 0; s < SPLITK; s++) {
            qv += qp[(long)s * slab + idx];
            kv += kp[(long)s * slab + idx];
        }
        partial = fmaf(qv, kv, partial);
    }
    float sim = block_sum(partial, red) * SCALE;
    float sg = 1.f / (1.f + __expf(-sim));

    for (int d = t; d < DD; d += 256) {
        long idx = (long)b * DD + d;
        float vv = bv[d];
        #pragma unroll
        for (int s = 0; s < SPLITK; s++) vv += vp[(long)s * slab + idx];
        x[idx] = fc[idx] - sg * vv;
    }
}

// ---------------------------------------------------------------------------
// v_diff = relu(vdraw + bc); vdwg2[b] = <v_diff[b], Wg2>
// ---------------------------------------------------------------------------
__global__ __launch_bounds__(256) void relu_wg2_kernel(
    const float* __restrict__ vdp, const float* __restrict__ bc,
    const float* __restrict__ Wg, float* __restrict__ vdiff,
    float* __restrict__ vdwg2)
{
    const int b = blockIdx.x;
    const int t = threadIdx.x;
    __shared__ float red[8];
    const long slab = (long)BB * DD;
    const float* Wg2 = Wg + DD;

    float partial = 0.f;
    for (int d = t; d < DD; d += 256) {
        long idx = (long)b * DD + d;
        float r = bc[d];
        #pragma unroll
        for (int s = 0; s < SPLITK; s++) r += vdp[(long)s * slab + idx];
        r = fmaxf(r, 0.f);
        vdiff[idx] = r;
        partial = fmaf(r, Wg2[d], partial);
    }
    float tot = block_sum(partial, red);
    if (t == 0) vdwg2[b] = tot;
}

// ---------------------------------------------------------------------------
// Final fused pass, warp-per-row (no barriers in the hot path):
//   each warp owns one (b,i) att row (1024 floats = 32 lanes x 8 float4),
//   g = sigmoid(att.Wg1 + vdwg2[b] + bg), out = att + rs*g*v_diff[b].
//   att row read once from DRAM, reused from registers for the output.
// ---------------------------------------------------------------------------
__global__ __launch_bounds__(256) void final_kernel(
    const float* __restrict__ att, const float* __restrict__ Wg,
    const float* __restrict__ vdiff, const float* __restrict__ vdwg2,
    const float* __restrict__ bg, const float* __restrict__ rs,
    float* __restrict__ out)
{
    const int warp = threadIdx.x >> 5;
    const int lane = threadIdx.x & 31;
    const int row  = blockIdx.x * 8 + warp;       // 0 .. B*NI-1
    const int b    = row >> 10;                   // row / NI_
    const long base = (long)row * DD;

    float4 a[8];
    float partial = 0.f;
    #pragma unroll
    for (int i = 0; i < 8; i++) {
        int d = (i * 32 + lane) * 4;
        a[i] = *reinterpret_cast<const float4*>(att + base + d);
        float4 wv = *reinterpret_cast<const float4*>(Wg + d);
        partial += a[i].x * wv.x + a[i].y * wv.y + a[i].z * wv.z + a[i].w * wv.w;
    }
    #pragma unroll
    for (int o = 16; o > 0; o >>= 1)
        partial += __shfl_xor_sync(0xffffffffu, partial, o);

    float g = 1.f / (1.f + __expf(-(partial + vdwg2[b] + bg[0])));
    float r = rs[0] * g;

    #pragma unroll
    for (int i = 0; i < 8; i++) {
        int d = (i * 32 + lane) * 4;
        float4 vd = *reinterpret_cast<const float4*>(vdiff + (long)b * DD + d);
        float4 o4;
        o4.x = fmaf(r, vd.x, a[i].x);
        o4.y = fmaf(r, vd.y, a[i].y);
        o4.z = fmaf(r, vd.z, a[i].z);
        o4.w = fmaf(r, vd.w, a[i].w);
        *reinterpret_cast<float4*>(out + base + d) = o4;
    }
}

// ---------------------------------------------------------------------------
// Launch
// ---------------------------------------------------------------------------
extern "C" void kernel_launch(void* const* d_in, const int* in_sizes, int n_in,
                              void* d_out, int out_size)
{
    const float* att  = (const float*)d_in[0];
    const float* fc   = (const float*)d_in[1];
    const float* pool = (const float*)d_in[2];
    const float* Wagg = (const float*)d_in[3];
    const float* Wq   = (const float*)d_in[4];
    const float* bq   = (const float*)d_in[5];
    const float* Wk   = (const float*)d_in[6];
    const float* bk   = (const float*)d_in[7];
    const float* Wv   = (const float*)d_in[8];
    const float* bv   = (const float*)d_in[9];
    const float* Wc   = (const float*)d_in[10];
    const float* bc   = (const float*)d_in[11];
    const float* Wg   = (const float*)d_in[12];
    const float* bg   = (const float*)d_in[13];
    const float* rs   = (const float*)d_in[14];
    float* out = (float*)d_out;

    float *qall_part, *scores_part, *weights, *vagg_part, *vagg;
    float *q_part, *k_part, *v_part, *x, *vdraw_part, *vdiff, *vdwg2;
    cudaGetSymbolAddress((void**)&qall_part,   g_qall_part);
    cudaGetSymbolAddress((void**)&scores_part, g_scores_part);
    cudaGetSymbolAddress((void**)&weights,     g_weights);
    cudaGetSymbolAddress((void**)&vagg_part,   g_vagg_part);
    cudaGetSymbolAddress((void**)&vagg,        g_vagg);
    cudaGetSymbolAddress((void**)&q_part,      g_q_part);
    cudaGetSymbolAddress((void**)&k_part,      g_k_part);
    cudaGetSymbolAddress((void**)&v_part,      g_v_part);
    cudaGetSymbolAddress((void**)&x,           g_x);
    cudaGetSymbolAddress((void**)&vdraw_part,  g_vdraw_part);
    cudaGetSymbolAddress((void**)&vdiff,       g_vdiff);
    cudaGetSymbolAddress((void**)&vdwg2,       g_vdwg2);

    const long BD   = (long)BB * DD;       // 32768
    const long RBD  = (long)RR * BD;       // 98304
    const long RBP  = (long)RR * BB * PP;  // 96000

    // 1) q_all[r,b,o] = vhat @ W_agg[r]^T  -> SPLITK slabs (left unreduced)
    gemm_kernel<<<dim3(16 * SPLITK, 1, RR), 128>>>(
        fc, DD, 0L, 1, 0L, Wagg, DD, (long)DD * DD,
        qall_part, DD, BD, RBD, DD, DD, 1.f, 0);

    // 2) scores[rb,p] = (sum-slabs q_all) @ pool^T * scale  (A-slab fusion)
    gemm_kernel<<<dim3(16 * SPLITK, 3, 1), 128>>>(
        qall_part, DD, 0L, SPLITK, RBD, pool, DD, 0L,
        scores_part, PP, 0L, RBP, PP, DD, SCALE, 0);

    // 3) softmax over P per row (sums SPLITK slabs internally)
    softmax_kernel<<<96, 256>>>(scores_part, weights);

    // 4) vagg[b,d] = (1/R) * sum_r weights[r] @ pool
    gemm_kernel<<<dim3(16 * SPLITK, 1, RR), 128>>>(
        weights, PP, (long)BB * PP, 1, 0L, pool, DD, 0L,
        vagg_part, DD, BD, RBD, DD, PP, 1.f / 3.f, 1);
    reduce_slabs_kernel<<<(int)((BD + 255) / 256), 256>>>(
        vagg_part, vagg, (int)BD, SPLITK * RR);

    // 5) q, k, v (left as SPLITK slabs; simx sums + adds biases)
    gemm_kernel<<<dim3(16 * SPLITK, 1, 1), 128>>>(
        fc, DD, 0L, 1, 0L, Wq, DD, 0L, q_part, DD, 0L, BD, DD, DD, 1.f, 0);
    gemm_kernel<<<dim3(16 * SPLITK, 1, 1), 128>>>(
        vagg, DD, 0L, 1, 0L, Wk, DD, 0L, k_part, DD, 0L, BD, DD, DD, 1.f, 0);
    gemm_kernel<<<dim3(16 * SPLITK, 1, 1), 128>>>(
        vagg, DD, 0L, 1, 0L, Wv, DD, 0L, v_part, DD, 0L, BD, DD, DD, 1.f, 0);

    // 6) sim + v_common + x = vhat - v_common
    simx_kernel<<<BB, 256>>>(q_part, k_part, v_part, bq, bk, bv, fc, x);

    // 7) vdraw = x @ Wc^T
    gemm_kernel<<<dim3(16 * SPLITK, 1, 1), 128>>>(
        x, DD, 0L, 1, 0L, Wc, DD, 0L, vdraw_part, DD, 0L, BD, DD, DD, 1.f, 0);

    // 8) v_diff = relu(vdraw + bc); vdwg2 = v_diff @ Wg2
    relu_wg2_kernel<<<BB, 256>>>(vdraw_part, bc, Wg, vdiff, vdwg2);

    // 9) fused gate + residual over att_feats (dominant, DRAM-bound)
    final_kernel<<<4096, 256>>>(att, Wg, vdiff, vdwg2, bg, rs, out);
}

// round 5
// speedup vs baseline: 1.5567x; 1.5567x over previous
#include <cuda_runtime.h>
#include <math.h>

// Problem constants
#define BB   32
#define DD   1024
#define NI_  1024
#define PP   1000
#define RR   3
#define SCALE 0.03125f   // 1/sqrt(1024)
#define SPLITK 8
#define KC   32

// ---------------------------------------------------------------------------
// Scratch (device globals; no allocation allowed)
// ---------------------------------------------------------------------------
__device__ float g_qall_part  [SPLITK * RR * BB * DD];
__device__ float g_scores_part[SPLITK * RR * BB * PP];
__device__ float g_weights    [RR * BB * PP];
__device__ float g_vagg_part  [SPLITK * RR * BB * DD];
__device__ float g_vagg       [BB * DD];
__device__ float g_q_part     [SPLITK * BB * DD];
__device__ float g_k_part     [SPLITK * BB * DD];
__device__ float g_v_part     [SPLITK * BB * DD];
__device__ float g_x          [BB * DD];
__device__ float g_vdraw_part [SPLITK * BB * DD];
__device__ float g_vdiff      [BB * DD];
__device__ float g_vdwg2      [BB];

// ---------------------------------------------------------------------------
// f32x2 packed helpers (FFMA2 — ptxas never emits this from C++)
// ---------------------------------------------------------------------------
__device__ __forceinline__ unsigned long long pack2(float x, float y) {
    unsigned long long r;
    asm("mov.b64 %0, {%1, %2};" : "=l"(r) : "f"(x), "f"(y));
    return r;
}
#define FMA2(acc, a, b) \
    asm("fma.rn.f32x2 %0, %1, %2, %3;" : "=l"(acc) : "l"(a), "l"(b), "l"(acc))

union U64F2 { unsigned long long u; float2 f; };

// ---------------------------------------------------------------------------
// Block reductions (small kernels only)
// ---------------------------------------------------------------------------
__device__ __forceinline__ float block_sum(float v, float* red) {
    #pragma unroll
    for (int o = 16; o > 0; o >>= 1) v += __shfl_xor_sync(0xffffffffu, v, o);
    int w = threadIdx.x >> 5, l = threadIdx.x & 31;
    if (l == 0) red[w] = v;
    __syncthreads();
    if (w == 0) {
        float x = (l < (int)(blockDim.x >> 5)) ? red[l] : 0.f;
        #pragma unroll
        for (int o = 4; o > 0; o >>= 1) x += __shfl_xor_sync(0xffffffffu, x, o);
        if (l == 0) red[0] = x;
    }
    __syncthreads();
    float r = red[0];
    __syncthreads();
    return r;
}

__device__ __forceinline__ float block_max(float v, float* red) {
    #pragma unroll
    for (int o = 16; o > 0; o >>= 1) v = fmaxf(v, __shfl_xor_sync(0xffffffffu, v, o));
    int w = threadIdx.x >> 5, l = threadIdx.x & 31;
    if (l == 0) red[w] = v;
    __syncthreads();
    if (w == 0) {
        float x = (l < (int)(blockDim.x >> 5)) ? red[l] : -1e30f;
        #pragma unroll
        for (int o = 4; o > 0; o >>= 1) x = fmaxf(x, __shfl_xor_sync(0xffffffffu, x, o));
        if (l == 0) red[0] = x;
    }
    __syncthreads();
    float r = red[0];
    __syncthreads();
    return r;
}

// ---------------------------------------------------------------------------
// GEMM core: C[m][n] = alpha * sum_k A[m][k] * Bop[k][n], 32x64 tile,
// 128 threads, 4x4 micro-tile done as 4x(2 f32x2), KC=32 chunks with
// smem double-buffering + register prefetch (1 barrier per chunk).
// A slab-sum fusion via nslabA (full chunks only at those call sites).
// ---------------------------------------------------------------------------
__device__ __forceinline__ void ldA(const float* __restrict__ Ap, int lda,
                                    int nslabA, long sAslab,
                                    int k0, int kcur, int t, float4* rA) {
    #pragma unroll
    for (int i = 0; i < 2; i++) {
        int f4 = t + 128 * i;
        int m  = f4 >> 3;
        int kq = (f4 & 7) << 2;
        const float* ap = Ap + (long)m * lda + k0 + kq;
        float4 av = make_float4(0.f, 0.f, 0.f, 0.f);
        if (kcur == KC) {
            av = *reinterpret_cast<const float4*>(ap);
            for (int s = 1; s < nslabA; s++) {
                float4 t4 = *reinterpret_cast<const float4*>(ap + (long)s * sAslab);
                av.x += t4.x; av.y += t4.y; av.z += t4.z; av.w += t4.w;
            }
        } else {          // only reached with nslabA == 1
            float* pv = &av.x;
            #pragma unroll
            for (int j = 0; j < 4; j++)
                if (kq + j < kcur) pv[j] = ap[j];
        }
        rA[i] = av;
    }
}

__device__ __forceinline__ void ldB(const float* __restrict__ Bp, int ldb,
                                    int N, int n0, int k0, int kcur, int bkn,
                                    int t, float4* rB) {
    if (!bkn) {           // B[N][K]
        #pragma unroll
        for (int i = 0; i < 4; i++) {
            int f4 = t + 128 * i;
            int n  = f4 >> 3;
            int kq = (f4 & 7) << 2;
            int gn = n0 + n;
            float4 bv = make_float4(0.f, 0.f, 0.f, 0.f);
            if (gn < N) {
                const float* bp = Bp + (long)gn * ldb + k0 + kq;
                if (kcur == KC) {
                    bv = *reinterpret_cast<const float4*>(bp);
                } else {
                    float* pv = &bv.x;
                    #pragma unroll
                    for (int j = 0; j < 4; j++)
                        if (kq + j < kcur) pv[j] = bp[j];
                }
            }
            rB[i] = bv;
        }
    } else {              // B[K][N]
        #pragma unroll
        for (int i = 0; i < 4; i++) {
            int f4 = t + 128 * i;
            int kc = f4 >> 4;
            int nq = (f4 & 15) << 2;
            int gn = n0 + nq;
            float4 bv = make_float4(0.f, 0.f, 0.f, 0.f);
            if (kc < kcur) {
                const float* bp = Bp + (long)(k0 + kc) * ldb + gn;
                if (gn + 3 < N) {
                    bv = *reinterpret_cast<const float4*>(bp);
                } else {
                    float* pv = &bv.x;
                    #pragma unroll
                    for (int j = 0; j < 4; j++)
                        if (gn + j < N) pv[j] = bp[j];
                }
            }
            rB[i] = bv;
        }
    }
}

__device__ __forceinline__ void stA(unsigned long long (*As2)[34], int t,
                                    const float4* rA) {
    #pragma unroll
    for (int i = 0; i < 2; i++) {
        int f4 = t + 128 * i;
        int m  = f4 >> 3;
        int kq = (f4 & 7) << 2;
        const float* pv = reinterpret_cast<const float*>(&rA[i]);
        #pragma unroll
        for (int j = 0; j < 4; j++)
            As2[kq + j][m] = pack2(pv[j], pv[j]);   // duplicated halves
    }
}

__device__ __forceinline__ void stB(float (*Bs)[68], int bkn, int t,
                                    const float4* rB) {
    if (!bkn) {
        #pragma unroll
        for (int i = 0; i < 4; i++) {
            int f4 = t + 128 * i;
            int n  = f4 >> 3;
            int kq = (f4 & 7) << 2;
            Bs[kq + 0][n] = rB[i].x;
            Bs[kq + 1][n] = rB[i].y;
            Bs[kq + 2][n] = rB[i].z;
            Bs[kq + 3][n] = rB[i].w;
        }
    } else {
        #pragma unroll
        for (int i = 0; i < 4; i++) {
            int f4 = t + 128 * i;
            int kc = f4 >> 4;
            int nq = (f4 & 15) << 2;
            *reinterpret_cast<float4*>(&Bs[kc][nq]) = rB[i];
        }
    }
}

__device__ __forceinline__ void gemm_core(
    const float* __restrict__ Ap, int lda, int nslabA, long sAslab,
    const float* __restrict__ Bp, int ldb,
    float* __restrict__ Cp, int ldc,
    int N, int K, float alpha, int bkn, int kp, int n0)
{
    __shared__ unsigned long long As2[2][KC][34];
    __shared__ float Bs[2][KC][68];

    const int t  = threadIdx.x;
    const int tm = t >> 4;
    const int tn = t & 15;

    unsigned long long acc[4][2];
    #pragma unroll
    for (int i = 0; i < 4; i++) { acc[i][0] = 0ull; acc[i][1] = 0ull; }

    const int nch = (K + KC - 1) / KC;
    float4 rA[2], rB[4];

    int c = kp;
    {
        int k0 = c * KC;
        int kcur = K - k0; if (kcur > KC) kcur = KC;
        ldA(Ap, lda, nslabA, sAslab, k0, kcur, t, rA);
        ldB(Bp, ldb, N, n0, k0, kcur, bkn, t, rB);
    }
    stA(As2[0], t, rA);
    stB(Bs[0], bkn, t, rB);
    __syncthreads();

    int p = 0;
    while (true) {
        int nxt = c + SPLITK;
        bool has = nxt < nch;
        if (has) {
            int k0 = nxt * KC;
            int kcur = K - k0; if (kcur > KC) kcur = KC;
            ldA(Ap, lda, nslabA, sAslab, k0, kcur, t, rA);
            ldB(Bp, ldb, N, n0, k0, kcur, bkn, t, rB);
        }
        // compute current buffer
        #pragma unroll
        for (int kc = 0; kc < KC; kc++) {
            ulonglong2 a01 = *reinterpret_cast<const ulonglong2*>(&As2[p][kc][tm << 2]);
            ulonglong2 a23 = *reinterpret_cast<const ulonglong2*>(&As2[p][kc][(tm << 2) + 2]);
            ulonglong2 b01 = *reinterpret_cast<const ulonglong2*>(&Bs[p][kc][tn << 2]);
            FMA2(acc[0][0], a01.x, b01.x); FMA2(acc[0][1], a01.x, b01.y);
            FMA2(acc[1][0], a01.y, b01.x); FMA2(acc[1][1], a01.y, b01.y);
            FMA2(acc[2][0], a23.x, b01.x); FMA2(acc[2][1], a23.x, b01.y);
            FMA2(acc[3][0], a23.y, b01.x); FMA2(acc[3][1], a23.y, b01.y);
        }
        if (!has) break;
        stA(As2[1 - p], t, rA);
        stB(Bs[1 - p], bkn, t, rB);
        __syncthreads();
        p ^= 1;
        c = nxt;
    }

    // epilogue: unpack + store partial slab (deterministic, no atomics)
    #pragma unroll
    for (int i = 0; i < 4; i++) {
        long rowoff = (long)((tm << 2) + i) * ldc;
        U64F2 u0, u1; u0.u = acc[i][0]; u1.u = acc[i][1];
        float v[4] = {u0.f.x, u0.f.y, u1.f.x, u1.f.y};
        #pragma unroll
        for (int j = 0; j < 4; j++) {
            int gn = n0 + (tn << 2) + j;
            if (gn < N) Cp[rowoff + gn] = v[j] * alpha;
        }
    }
}

// ---------------------------------------------------------------------------
// Generic wrapper: grid.x = ntilesN*SPLITK, grid.y = M/32, grid.z = batch
// ---------------------------------------------------------------------------
__global__ __launch_bounds__(128) void gemm_kernel(
    const float* __restrict__ A, int lda, long sAz, int nslabA, long sAslab,
    const float* __restrict__ B, int ldb, long sBz,
    float* __restrict__ C, int ldc, long sCz, long sCkp,
    int N, int K, float alpha, int bkn)
{
    const int nt = blockIdx.x / SPLITK;
    const int kp = blockIdx.x % SPLITK;
    const int n0 = nt * 64;
    const int m0 = blockIdx.y * 32;
    const float* Ap = A + (long)blockIdx.z * sAz + (long)m0 * lda;
    const float* Bp = B + (long)blockIdx.z * sBz;
    float*       Cp = C + (long)kp * sCkp + (long)blockIdx.z * sCz + (long)m0 * ldc;
    gemm_core(Ap, lda, nslabA, sAslab, Bp, ldb, Cp, ldc, N, K, alpha, bkn, kp, n0);
}

// ---------------------------------------------------------------------------
// Merged q/k/v wrapper: z=0: fc@Wq, z=1: vagg@Wk, z=2: vagg@Wv
// ---------------------------------------------------------------------------
__global__ __launch_bounds__(128) void qkv_kernel(
    const float* __restrict__ fc, const float* __restrict__ vagg,
    const float* __restrict__ Wq, const float* __restrict__ Wk,
    const float* __restrict__ Wv,
    float* __restrict__ qp, float* __restrict__ kp_, float* __restrict__ vp)
{
    const int z  = blockIdx.z;
    const int nt = blockIdx.x / SPLITK;
    const int kp = blockIdx.x % SPLITK;
    const int n0 = nt * 64;
    const float* A = (z == 0) ? fc : vagg;
    const float* B = (z == 0) ? Wq : ((z == 1) ? Wk : Wv);
    float*       C = (z == 0) ? qp : ((z == 1) ? kp_ : vp);
    float*       Cp = C + (long)kp * (long)BB * DD;
    gemm_core(A, DD, 1, 0L, B, DD, Cp, DD, DD, DD, 1.f, 0, kp, n0);
}

// ---------------------------------------------------------------------------
// Sum nslabs contiguous slabs of `elems` floats
// ---------------------------------------------------------------------------
__global__ __launch_bounds__(256) void reduce_slabs_kernel(
    const float* __restrict__ src, float* __restrict__ dst, int elems, int nslabs)
{
    int i = blockIdx.x * 256 + threadIdx.x;
    if (i < elems) {
        float s = 0.f;
        for (int k = 0; k < nslabs; k++) s += src[(long)k * elems + i];
        dst[i] = s;
    }
}

// ---------------------------------------------------------------------------
// Softmax over P for each of the 96 rows; input = SPLITK slabs of scores
// ---------------------------------------------------------------------------
__global__ __launch_bounds__(256) void softmax_kernel(
    const float* __restrict__ sp, float* __restrict__ w)
{
    const int row = blockIdx.x;
    const int t = threadIdx.x;
    __shared__ float buf[PP];
    __shared__ float red[8];
    const long base = (long)row * PP;
    const long slab = (long)RR * BB * PP;

    float mx = -1e30f;
    for (int p = t; p < PP; p += 256) {
        float s = 0.f;
        #pragma unroll
        for (int k = 0; k < SPLITK; k++) s += sp[(long)k * slab + base + p];
        buf[p] = s;
        mx = fmaxf(mx, s);
    }
    float m = block_max(mx, red);

    float sum = 0.f;
    for (int p = t; p < PP; p += 256) {
        float e = __expf(buf[p] - m);
        buf[p] = e;
        sum += e;
    }
    float S = block_sum(sum, red);
    float inv = 1.f / S;
    for (int p = t; p < PP; p += 256) w[base + p] = buf[p] * inv;
}

// ---------------------------------------------------------------------------
// sim = <q+bq, k+bk>*scale per batch; x = vhat - sigmoid(sim)*(v+bv)
// ---------------------------------------------------------------------------
__global__ __launch_bounds__(256) void simx_kernel(
    const float* __restrict__ qp, const float* __restrict__ kp,
    const float* __restrict__ vp,
    const float* __restrict__ bq, const float* __restrict__ bk,
    const float* __restrict__ bv,
    const float* __restrict__ fc, float* __restrict__ x)
{
    const int b = blockIdx.x;
    const int t = threadIdx.x;
    __shared__ float red[8];
    const long slab = (long)BB * DD;

    float partial = 0.f;
    for (int d = t; d < DD; d += 256) {
        long idx = (long)b * DD + d;
        float qv = bq[d], kv = bk[d];
        #pragma unroll
        for (int s = 0; s < SPLITK; s++) {
            qv += qp[(long)s * slab + idx];
            kv += kp[(long)s * slab + idx];
        }
        partial = fmaf(qv, kv, partial);
    }
    float sim = block_sum(partial, red) * SCALE;
    float sg = 1.f / (1.f + __expf(-sim));

    for (int d = t; d < DD; d += 256) {
        long idx = (long)b * DD + d;
        float vv = bv[d];
        #pragma unroll
        for (int s = 0; s < SPLITK; s++) vv += vp[(long)s * slab + idx];
        x[idx] = fc[idx] - sg * vv;
    }
}

// ---------------------------------------------------------------------------
// v_diff = relu(vdraw + bc); vdwg2[b] = <v_diff[b], Wg2>
// ---------------------------------------------------------------------------
__global__ __launch_bounds__(256) void relu_wg2_kernel(
    const float* __restrict__ vdp, const float* __restrict__ bc,
    const float* __restrict__ Wg, float* __restrict__ vdiff,
    float* __restrict__ vdwg2)
{
    const int b = blockIdx.x;
    const int t = threadIdx.x;
    __shared__ float red[8];
    const long slab = (long)BB * DD;
    const float* Wg2 = Wg + DD;

    float partial = 0.f;
    for (int d = t; d < DD; d += 256) {
        long idx = (long)b * DD + d;
        float r = bc[d];
        #pragma unroll
        for (int s = 0; s < SPLITK; s++) r += vdp[(long)s * slab + idx];
        r = fmaxf(r, 0.f);
        vdiff[idx] = r;
        partial = fmaf(r, Wg2[d], partial);
    }
    float tot = block_sum(partial, red);
    if (t == 0) vdwg2[b] = tot;
}

// ---------------------------------------------------------------------------
// Final fused pass, warp-per-row (no barriers in the hot path).
// ---------------------------------------------------------------------------
__global__ __launch_bounds__(256) void final_kernel(
    const float* __restrict__ att, const float* __restrict__ Wg,
    const float* __restrict__ vdiff, const float* __restrict__ vdwg2,
    const float* __restrict__ bg, const float* __restrict__ rs,
    float* __restrict__ out)
{
    const int warp = threadIdx.x >> 5;
    const int lane = threadIdx.x & 31;
    const int row  = blockIdx.x * 8 + warp;       // 0 .. B*NI-1
    const int b    = row >> 10;                   // row / NI_
    const long base = (long)row * DD;

    float4 a[8];
    float partial = 0.f;
    #pragma unroll
    for (int i = 0; i < 8; i++) {
        int d = (i * 32 + lane) * 4;
        a[i] = *reinterpret_cast<const float4*>(att + base + d);
        float4 wv = *reinterpret_cast<const float4*>(Wg + d);
        partial += a[i].x * wv.x + a[i].y * wv.y + a[i].z * wv.z + a[i].w * wv.w;
    }
    #pragma unroll
    for (int o = 16; o > 0; o >>= 1)
        partial += __shfl_xor_sync(0xffffffffu, partial, o);

    float g = 1.f / (1.f + __expf(-(partial + vdwg2[b] + bg[0])));
    float r = rs[0] * g;

    #pragma unroll
    for (int i = 0; i < 8; i++) {
        int d = (i * 32 + lane) * 4;
        float4 vd = *reinterpret_cast<const float4*>(vdiff + (long)b * DD + d);
        float4 o4;
        o4.x = fmaf(r, vd.x, a[i].x);
        o4.y = fmaf(r, vd.y, a[i].y);
        o4.z = fmaf(r, vd.z, a[i].z);
        o4.w = fmaf(r, vd.w, a[i].w);
        *reinterpret_cast<float4*>(out + base + d) = o4;
    }
}

// ---------------------------------------------------------------------------
// Launch
// ---------------------------------------------------------------------------
extern "C" void kernel_launch(void* const* d_in, const int* in_sizes, int n_in,
                              void* d_out, int out_size)
{
    const float* att  = (const float*)d_in[0];
    const float* fc   = (const float*)d_in[1];
    const float* pool = (const float*)d_in[2];
    const float* Wagg = (const float*)d_in[3];
    const float* Wq   = (const float*)d_in[4];
    const float* bq   = (const float*)d_in[5];
    const float* Wk   = (const float*)d_in[6];
    const float* bk   = (const float*)d_in[7];
    const float* Wv   = (const float*)d_in[8];
    const float* bv   = (const float*)d_in[9];
    const float* Wc   = (const float*)d_in[10];
    const float* bc   = (const float*)d_in[11];
    const float* Wg   = (const float*)d_in[12];
    const float* bg   = (const float*)d_in[13];
    const float* rs   = (const float*)d_in[14];
    float* out = (float*)d_out;

    float *qall_part, *scores_part, *weights, *vagg_part, *vagg;
    float *q_part, *k_part, *v_part, *x, *vdraw_part, *vdiff, *vdwg2;
    cudaGetSymbolAddress((void**)&qall_part,   g_qall_part);
    cudaGetSymbolAddress((void**)&scores_part, g_scores_part);
    cudaGetSymbolAddress((void**)&weights,     g_weights);
    cudaGetSymbolAddress((void**)&vagg_part,   g_vagg_part);
    cudaGetSymbolAddress((void**)&vagg,        g_vagg);
    cudaGetSymbolAddress((void**)&q_part,      g_q_part);
    cudaGetSymbolAddress((void**)&k_part,      g_k_part);
    cudaGetSymbolAddress((void**)&v_part,      g_v_part);
    cudaGetSymbolAddress((void**)&x,           g_x);
    cudaGetSymbolAddress((void**)&vdraw_part,  g_vdraw_part);
    cudaGetSymbolAddress((void**)&vdiff,       g_vdiff);
    cudaGetSymbolAddress((void**)&vdwg2,       g_vdwg2);

    const long BD   = (long)BB * DD;       // 32768
    const long RBD  = (long)RR * BD;       // 98304
    const long RBP  = (long)RR * BB * PP;  // 96000

    // 1) q_all[r,b,o] = vhat @ W_agg[r]^T  -> SPLITK slabs (left unreduced)
    gemm_kernel<<<dim3(16 * SPLITK, 1, RR), 128>>>(
        fc, DD, 0L, 1, 0L, Wagg, DD, (long)DD * DD,
        qall_part, DD, BD, RBD, DD, DD, 1.f, 0);

    // 2) scores[rb,p] = (sum-slabs q_all) @ pool^T * scale  (A-slab fusion)
    gemm_kernel<<<dim3(16 * SPLITK, 3, 1), 128>>>(
        qall_part, DD, 0L, SPLITK, RBD, pool, DD, 0L,
        scores_part, PP, 0L, RBP, PP, DD, SCALE, 0);

    // 3) softmax over P per row (sums SPLITK slabs internally)
    softmax_kernel<<<96, 256>>>(scores_part, weights);

    // 4) vagg[b,d] = (1/R) * sum_r weights[r] @ pool
    gemm_kernel<<<dim3(16 * SPLITK, 1, RR), 128>>>(
        weights, PP, (long)BB * PP, 1, 0L, pool, DD, 0L,
        vagg_part, DD, BD, RBD, DD, PP, 1.f / 3.f, 1);
    reduce_slabs_kernel<<<(int)((BD + 255) / 256), 256>>>(
        vagg_part, vagg, (int)BD, SPLITK * RR);

    // 5) q, k, v in ONE launch (z planes), left as SPLITK slabs
    qkv_kernel<<<dim3(16 * SPLITK, 1, 3), 128>>>(
        fc, vagg, Wq, Wk, Wv, q_part, k_part, v_part);

    // 6) sim + v_common + x = vhat - v_common
    simx_kernel<<<BB, 256>>>(q_part, k_part, v_part, bq, bk, bv, fc, x);

    // 7) vdraw = x @ Wc^T
    gemm_kernel<<<dim3(16 * SPLITK, 1, 1), 128>>>(
        x, DD, 0L, 1, 0L, Wc, DD, 0L, vdraw_part, DD, 0L, BD, DD, DD, 1.f, 0);

    // 8) v_diff = relu(vdraw + bc); vdwg2 = v_diff @ Wg2
    relu_wg2_kernel<<<BB, 256>>>(vdraw_part, bc, Wg, vdiff, vdwg2);

    // 9) fused gate + residual over att_feats (dominant, DRAM-bound)
    final_kernel<<<4096, 256>>>(att, Wg, vdiff, vdwg2, bg, rs, out);
}